// round 11
// baseline (speedup 1.0000x reference)
#include <cuda_runtime.h>
#include <cuda_fp16.h>
#include <cstdint>

// DistMult edge scorer:
//   out[e] = sigmoid( sum_d z[src,d] * rel[rel_id,d] * z[dst,d] )
// Inputs:
//   d_in[0]: z          float32 [100000, 128]
//   d_in[1]: edge_index int32   [2, E]
//   d_in[2]: rel_id     int32   [E]
//   d_in[3]: rel        float32 [64, 128]
// Output: float32 [E]
//
//  1) convert_kernel: z, rel -> fp16 mirrors (8 floats/thread, one 16B store).
//  2) distmult_h: 8 lanes/edge, 4 edges/warp-pass, unroll 2, HFMA2 math with
//     4 independent half2 accumulators. NEW: distance-1 software pipeline on
//     the index loads — pass m's data loads issue immediately, pass m+1's
//     index loads issue next, pass m's math covers their latency.

#define D 128
#define NZ_MAX (100000 * D)
#define NR_MAX (64 * D)
#define FULL 0xFFFFFFFFu

__device__ __half g_zh[NZ_MAX];
__device__ __half g_rh[NR_MAX];

// ---------------- conversion: fp32 -> fp16 mirrors ----------------
__device__ __forceinline__ uint4 cvt8(float4 v0, float4 v1) {
    __half2 h0 = __floats2half2_rn(v0.x, v0.y);
    __half2 h1 = __floats2half2_rn(v0.z, v0.w);
    __half2 h2 = __floats2half2_rn(v1.x, v1.y);
    __half2 h3 = __floats2half2_rn(v1.z, v1.w);
    uint4 o;
    o.x = *reinterpret_cast<unsigned*>(&h0);
    o.y = *reinterpret_cast<unsigned*>(&h1);
    o.z = *reinterpret_cast<unsigned*>(&h2);
    o.w = *reinterpret_cast<unsigned*>(&h3);
    return o;
}

__global__ __launch_bounds__(256) void convert_kernel(
    const float* __restrict__ z, const float* __restrict__ rel,
    int nz, int nr)
{
    int i = blockIdx.x * blockDim.x + threadIdx.x;   // 8 floats per thread
    int nz8 = nz >> 3;
    int nr8 = nr >> 3;
    if (i < nz8) {
        const float4* zp = reinterpret_cast<const float4*>(z);
        reinterpret_cast<uint4*>(g_zh)[i] = cvt8(zp[2 * i], zp[2 * i + 1]);
    } else if (i < nz8 + nr8) {
        int k = i - nz8;
        const float4* rp = reinterpret_cast<const float4*>(rel);
        reinterpret_cast<uint4*>(g_rh)[k] = cvt8(rp[2 * k], rp[2 * k + 1]);
    }
}

// ---------------- main kernel ----------------

__device__ __forceinline__ __half2 h2_of(unsigned u) {
    return *reinterpret_cast<__half2*>(&u);
}

__global__ __launch_bounds__(256) void distmult_h(
    const int* __restrict__ edge_index,  // [2, E]
    const int* __restrict__ rel_id,      // [E]
    float* __restrict__ out,
    int E)
{
    int warp_id = (blockIdx.x * blockDim.x + threadIdx.x) >> 5;
    int lane = threadIdx.x & 31;
    int g = lane >> 3;                   // edge group 0..3
    int j = lane & 7;                    // lane within group
    int base = warp_id << 5;             // 32 edges per warp
    if (base >= E) return;

    const uint4* zh = reinterpret_cast<const uint4*>(g_zh);  // 16 uint4 per row
    const uint4* rh = reinterpret_cast<const uint4*>(g_rh);

    // Pipeline prologue: pass 0's indices.
    int e = base + g;
    int s = edge_index[e];
    int d = edge_index[E + e];
    int r = rel_id[e];

    #pragma unroll 2
    for (int m = 0; m < 8; ++m) {
        const uint4* zs = zh + (size_t)s * 16;   // 256B row = 16 uint4
        const uint4* zd = zh + (size_t)d * 16;
        const uint4* rr = rh + (size_t)r * 16;

        // Pass m data loads: 6 independent LDG.128, each = 4 full 128B lines.
        uint4 A0 = zs[j], A1 = zs[j + 8];
        uint4 B0 = zd[j], B1 = zd[j + 8];
        uint4 C0 = rr[j], C1 = rr[j + 8];

        int eo = e;                      // edge this pass writes
        // Pass m+1 index loads (latency hidden by pass m math below).
        if (m < 7) {
            e = base + ((m + 1) << 2) + g;
            s = edge_index[e];
            d = edge_index[E + e];
            r = rel_id[e];
        }

        // 4 independent half2 accumulators; chains of length 2.
        __half2 acc0 = __hmul2(__hmul2(h2_of(A0.x), h2_of(C0.x)), h2_of(B0.x));
        __half2 acc1 = __hmul2(__hmul2(h2_of(A0.y), h2_of(C0.y)), h2_of(B0.y));
        __half2 acc2 = __hmul2(__hmul2(h2_of(A0.z), h2_of(C0.z)), h2_of(B0.z));
        __half2 acc3 = __hmul2(__hmul2(h2_of(A0.w), h2_of(C0.w)), h2_of(B0.w));
        acc0 = __hfma2(__hmul2(h2_of(A1.x), h2_of(C1.x)), h2_of(B1.x), acc0);
        acc1 = __hfma2(__hmul2(h2_of(A1.y), h2_of(C1.y)), h2_of(B1.y), acc1);
        acc2 = __hfma2(__hmul2(h2_of(A1.z), h2_of(C1.z)), h2_of(B1.z), acc2);
        acc3 = __hfma2(__hmul2(h2_of(A1.w), h2_of(C1.w)), h2_of(B1.w), acc3);

        // Pairwise fp16 combine, fp32 epilogue.
        __half2 s01 = __hadd2(acc0, acc1);
        __half2 s23 = __hadd2(acc2, acc3);
        float2 f01 = __half22float2(s01);
        float2 f23 = __half22float2(s23);
        float acc = (f01.x + f01.y) + (f23.x + f23.y);

        // Reduce over 8-lane group (fp32); 4 edges share the same 3 shfls.
        acc += __shfl_xor_sync(FULL, acc, 4);
        acc += __shfl_xor_sync(FULL, acc, 2);
        acc += __shfl_xor_sync(FULL, acc, 1);

        if (j == 0) {
            // Lanes 0,8,16,24 -> 4 consecutive floats, one wavefront.
            out[eo] = 1.0f / (1.0f + __expf(-acc));
        }
    }
}

extern "C" void kernel_launch(void* const* d_in, const int* in_sizes, int n_in,
                              void* d_out, int out_size)
{
    const float* z          = (const float*)d_in[0];
    const int*   edge_index = (const int*)d_in[1];
    const int*   rel_id     = (const int*)d_in[2];
    const float* rel        = (const float*)d_in[3];
    float*       out        = (float*)d_out;

    int nz = in_sizes[0];            // z element count (<= NZ_MAX)
    int nr = in_sizes[3];            // rel element count
    int E  = in_sizes[2];

    if (nz > NZ_MAX) nz = NZ_MAX;
    if (nr > NR_MAX) nr = NR_MAX;

    // 1) fp32 -> fp16 mirrors (8 floats per thread, one 16B store)
    {
        int work = (nz >> 3) + (nr >> 3);
        int threads = 256;
        int blocks = (work + threads - 1) / threads;
        convert_kernel<<<blocks, threads>>>(z, rel, nz, nr);
    }

    // 2) edge scoring (E assumed multiple of 32; full grid of 32-edge warps)
    {
        const int threads = 256;                 // 8 warps/block, 32 edges/warp
        int edges_per_block = (threads / 32) * 32;
        int blocks = (E + edges_per_block - 1) / edges_per_block;
        distmult_h<<<blocks, threads>>>(edge_index, rel_id, out, E);
    }
}

// round 12
// speedup vs baseline: 1.0074x; 1.0074x over previous
#include <cuda_runtime.h>
#include <cuda_fp16.h>
#include <cstdint>

// DistMult edge scorer:
//   out[e] = sigmoid( sum_d z[src,d] * rel[rel_id,d] * z[dst,d] )
// Inputs:
//   d_in[0]: z          float32 [100000, 128]
//   d_in[1]: edge_index int32   [2, E]
//   d_in[2]: rel_id     int32   [E]
//   d_in[3]: rel        float32 [64, 128]
// Output: float32 [E]
//
//  1) convert_kernel: z, rel -> fp16 mirrors (8 floats/thread, one 16B store).
//  2) distmult_h: 8 lanes/edge, 4 edges/warp-pass, unroll 2, HFMA2 math with
//     4 independent half2 accumulators. NEW: distance-1 software pipeline on
//     the index loads — pass m's data loads issue immediately, pass m+1's
//     index loads issue next, pass m's math covers their latency.

#define D 128
#define NZ_MAX (100000 * D)
#define NR_MAX (64 * D)
#define FULL 0xFFFFFFFFu

__device__ __half g_zh[NZ_MAX];
__device__ __half g_rh[NR_MAX];

// ---------------- conversion: fp32 -> fp16 mirrors ----------------
__device__ __forceinline__ uint4 cvt8(float4 v0, float4 v1) {
    __half2 h0 = __floats2half2_rn(v0.x, v0.y);
    __half2 h1 = __floats2half2_rn(v0.z, v0.w);
    __half2 h2 = __floats2half2_rn(v1.x, v1.y);
    __half2 h3 = __floats2half2_rn(v1.z, v1.w);
    uint4 o;
    o.x = *reinterpret_cast<unsigned*>(&h0);
    o.y = *reinterpret_cast<unsigned*>(&h1);
    o.z = *reinterpret_cast<unsigned*>(&h2);
    o.w = *reinterpret_cast<unsigned*>(&h3);
    return o;
}

__global__ __launch_bounds__(256) void convert_kernel(
    const float* __restrict__ z, const float* __restrict__ rel,
    int nz, int nr)
{
    int i = blockIdx.x * blockDim.x + threadIdx.x;   // 8 floats per thread
    int nz8 = nz >> 3;
    int nr8 = nr >> 3;
    if (i < nz8) {
        const float4* zp = reinterpret_cast<const float4*>(z);
        reinterpret_cast<uint4*>(g_zh)[i] = cvt8(zp[2 * i], zp[2 * i + 1]);
    } else if (i < nz8 + nr8) {
        int k = i - nz8;
        const float4* rp = reinterpret_cast<const float4*>(rel);
        reinterpret_cast<uint4*>(g_rh)[k] = cvt8(rp[2 * k], rp[2 * k + 1]);
    }
}

// ---------------- main kernel ----------------

__device__ __forceinline__ __half2 h2_of(unsigned u) {
    return *reinterpret_cast<__half2*>(&u);
}

__global__ __launch_bounds__(256) void distmult_h(
    const int* __restrict__ edge_index,  // [2, E]
    const int* __restrict__ rel_id,      // [E]
    float* __restrict__ out,
    int E)
{
    int warp_id = (blockIdx.x * blockDim.x + threadIdx.x) >> 5;
    int lane = threadIdx.x & 31;
    int g = lane >> 3;                   // edge group 0..3
    int j = lane & 7;                    // lane within group
    int base = warp_id << 5;             // 32 edges per warp
    if (base >= E) return;

    const uint4* zh = reinterpret_cast<const uint4*>(g_zh);  // 16 uint4 per row
    const uint4* rh = reinterpret_cast<const uint4*>(g_rh);

    // Pipeline prologue: pass 0's indices.
    int e = base + g;
    int s = edge_index[e];
    int d = edge_index[E + e];
    int r = rel_id[e];

    #pragma unroll 2
    for (int m = 0; m < 8; ++m) {
        const uint4* zs = zh + (size_t)s * 16;   // 256B row = 16 uint4
        const uint4* zd = zh + (size_t)d * 16;
        const uint4* rr = rh + (size_t)r * 16;

        // Pass m data loads: 6 independent LDG.128, each = 4 full 128B lines.
        uint4 A0 = zs[j], A1 = zs[j + 8];
        uint4 B0 = zd[j], B1 = zd[j + 8];
        uint4 C0 = rr[j], C1 = rr[j + 8];

        int eo = e;                      // edge this pass writes
        // Pass m+1 index loads (latency hidden by pass m math below).
        if (m < 7) {
            e = base + ((m + 1) << 2) + g;
            s = edge_index[e];
            d = edge_index[E + e];
            r = rel_id[e];
        }

        // 4 independent half2 accumulators; chains of length 2.
        __half2 acc0 = __hmul2(__hmul2(h2_of(A0.x), h2_of(C0.x)), h2_of(B0.x));
        __half2 acc1 = __hmul2(__hmul2(h2_of(A0.y), h2_of(C0.y)), h2_of(B0.y));
        __half2 acc2 = __hmul2(__hmul2(h2_of(A0.z), h2_of(C0.z)), h2_of(B0.z));
        __half2 acc3 = __hmul2(__hmul2(h2_of(A0.w), h2_of(C0.w)), h2_of(B0.w));
        acc0 = __hfma2(__hmul2(h2_of(A1.x), h2_of(C1.x)), h2_of(B1.x), acc0);
        acc1 = __hfma2(__hmul2(h2_of(A1.y), h2_of(C1.y)), h2_of(B1.y), acc1);
        acc2 = __hfma2(__hmul2(h2_of(A1.z), h2_of(C1.z)), h2_of(B1.z), acc2);
        acc3 = __hfma2(__hmul2(h2_of(A1.w), h2_of(C1.w)), h2_of(B1.w), acc3);

        // Pairwise fp16 combine, fp32 epilogue.
        __half2 s01 = __hadd2(acc0, acc1);
        __half2 s23 = __hadd2(acc2, acc3);
        float2 f01 = __half22float2(s01);
        float2 f23 = __half22float2(s23);
        float acc = (f01.x + f01.y) + (f23.x + f23.y);

        // Reduce over 8-lane group (fp32); 4 edges share the same 3 shfls.
        acc += __shfl_xor_sync(FULL, acc, 4);
        acc += __shfl_xor_sync(FULL, acc, 2);
        acc += __shfl_xor_sync(FULL, acc, 1);

        if (j == 0) {
            // Lanes 0,8,16,24 -> 4 consecutive floats, one wavefront.
            out[eo] = 1.0f / (1.0f + __expf(-acc));
        }
    }
}

extern "C" void kernel_launch(void* const* d_in, const int* in_sizes, int n_in,
                              void* d_out, int out_size)
{
    const float* z          = (const float*)d_in[0];
    const int*   edge_index = (const int*)d_in[1];
    const int*   rel_id     = (const int*)d_in[2];
    const float* rel        = (const float*)d_in[3];
    float*       out        = (float*)d_out;

    int nz = in_sizes[0];            // z element count (<= NZ_MAX)
    int nr = in_sizes[3];            // rel element count
    int E  = in_sizes[2];

    if (nz > NZ_MAX) nz = NZ_MAX;
    if (nr > NR_MAX) nr = NR_MAX;

    // 1) fp32 -> fp16 mirrors (8 floats per thread, one 16B store)
    {
        int work = (nz >> 3) + (nr >> 3);
        int threads = 256;
        int blocks = (work + threads - 1) / threads;
        convert_kernel<<<blocks, threads>>>(z, rel, nz, nr);
    }

    // 2) edge scoring (E assumed multiple of 32; full grid of 32-edge warps)
    {
        const int threads = 256;                 // 8 warps/block, 32 edges/warp
        int edges_per_block = (threads / 32) * 32;
        int blocks = (E + edges_per_block - 1) / edges_per_block;
        distmult_h<<<blocks, threads>>>(edge_index, rel_id, out, E);
    }
}

// round 13
// speedup vs baseline: 1.0086x; 1.0012x over previous
#include <cuda_runtime.h>
#include <cuda_fp16.h>
#include <cstdint>

// DistMult edge scorer:
//   out[e] = sigmoid( sum_d z[src,d] * rel[rel_id,d] * z[dst,d] )
// Inputs:
//   d_in[0]: z          float32 [100000, 128]
//   d_in[1]: edge_index int32   [2, E]
//   d_in[2]: rel_id     int32   [E]
//   d_in[3]: rel        float32 [64, 128]
// Output: float32 [E]
//
//  1) convert_kernel: z, rel -> fp16 mirrors (8 floats/thread, one 16B store).
//  2) distmult_h: 8 lanes/edge, 4 edges/warp-pass, unroll 2, HFMA2 math with
//     4 independent half2 accumulators. NEW: distance-1 software pipeline on
//     the index loads — pass m's data loads issue immediately, pass m+1's
//     index loads issue next, pass m's math covers their latency.

#define D 128
#define NZ_MAX (100000 * D)
#define NR_MAX (64 * D)
#define FULL 0xFFFFFFFFu

__device__ __half g_zh[NZ_MAX];
__device__ __half g_rh[NR_MAX];

// ---------------- conversion: fp32 -> fp16 mirrors ----------------
__device__ __forceinline__ uint4 cvt8(float4 v0, float4 v1) {
    __half2 h0 = __floats2half2_rn(v0.x, v0.y);
    __half2 h1 = __floats2half2_rn(v0.z, v0.w);
    __half2 h2 = __floats2half2_rn(v1.x, v1.y);
    __half2 h3 = __floats2half2_rn(v1.z, v1.w);
    uint4 o;
    o.x = *reinterpret_cast<unsigned*>(&h0);
    o.y = *reinterpret_cast<unsigned*>(&h1);
    o.z = *reinterpret_cast<unsigned*>(&h2);
    o.w = *reinterpret_cast<unsigned*>(&h3);
    return o;
}

__global__ __launch_bounds__(256) void convert_kernel(
    const float* __restrict__ z, const float* __restrict__ rel,
    int nz, int nr)
{
    int i = blockIdx.x * blockDim.x + threadIdx.x;   // 8 floats per thread
    int nz8 = nz >> 3;
    int nr8 = nr >> 3;
    if (i < nz8) {
        const float4* zp = reinterpret_cast<const float4*>(z);
        reinterpret_cast<uint4*>(g_zh)[i] = cvt8(zp[2 * i], zp[2 * i + 1]);
    } else if (i < nz8 + nr8) {
        int k = i - nz8;
        const float4* rp = reinterpret_cast<const float4*>(rel);
        reinterpret_cast<uint4*>(g_rh)[k] = cvt8(rp[2 * k], rp[2 * k + 1]);
    }
}

// ---------------- main kernel ----------------

__device__ __forceinline__ __half2 h2_of(unsigned u) {
    return *reinterpret_cast<__half2*>(&u);
}

__global__ __launch_bounds__(256) void distmult_h(
    const int* __restrict__ edge_index,  // [2, E]
    const int* __restrict__ rel_id,      // [E]
    float* __restrict__ out,
    int E)
{
    int warp_id = (blockIdx.x * blockDim.x + threadIdx.x) >> 5;
    int lane = threadIdx.x & 31;
    int g = lane >> 3;                   // edge group 0..3
    int j = lane & 7;                    // lane within group
    int base = warp_id << 5;             // 32 edges per warp
    if (base >= E) return;

    const uint4* zh = reinterpret_cast<const uint4*>(g_zh);  // 16 uint4 per row
    const uint4* rh = reinterpret_cast<const uint4*>(g_rh);

    // Pipeline prologue: pass 0's indices.
    int e = base + g;
    int s = edge_index[e];
    int d = edge_index[E + e];
    int r = rel_id[e];

    #pragma unroll 2
    for (int m = 0; m < 8; ++m) {
        const uint4* zs = zh + (size_t)s * 16;   // 256B row = 16 uint4
        const uint4* zd = zh + (size_t)d * 16;
        const uint4* rr = rh + (size_t)r * 16;

        // Pass m data loads: 6 independent LDG.128, each = 4 full 128B lines.
        uint4 A0 = zs[j], A1 = zs[j + 8];
        uint4 B0 = zd[j], B1 = zd[j + 8];
        uint4 C0 = rr[j], C1 = rr[j + 8];

        int eo = e;                      // edge this pass writes
        // Pass m+1 index loads (latency hidden by pass m math below).
        if (m < 7) {
            e = base + ((m + 1) << 2) + g;
            s = edge_index[e];
            d = edge_index[E + e];
            r = rel_id[e];
        }

        // 4 independent half2 accumulators; chains of length 2.
        __half2 acc0 = __hmul2(__hmul2(h2_of(A0.x), h2_of(C0.x)), h2_of(B0.x));
        __half2 acc1 = __hmul2(__hmul2(h2_of(A0.y), h2_of(C0.y)), h2_of(B0.y));
        __half2 acc2 = __hmul2(__hmul2(h2_of(A0.z), h2_of(C0.z)), h2_of(B0.z));
        __half2 acc3 = __hmul2(__hmul2(h2_of(A0.w), h2_of(C0.w)), h2_of(B0.w));
        acc0 = __hfma2(__hmul2(h2_of(A1.x), h2_of(C1.x)), h2_of(B1.x), acc0);
        acc1 = __hfma2(__hmul2(h2_of(A1.y), h2_of(C1.y)), h2_of(B1.y), acc1);
        acc2 = __hfma2(__hmul2(h2_of(A1.z), h2_of(C1.z)), h2_of(B1.z), acc2);
        acc3 = __hfma2(__hmul2(h2_of(A1.w), h2_of(C1.w)), h2_of(B1.w), acc3);

        // Pairwise fp16 combine, fp32 epilogue.
        __half2 s01 = __hadd2(acc0, acc1);
        __half2 s23 = __hadd2(acc2, acc3);
        float2 f01 = __half22float2(s01);
        float2 f23 = __half22float2(s23);
        float acc = (f01.x + f01.y) + (f23.x + f23.y);

        // Reduce over 8-lane group (fp32); 4 edges share the same 3 shfls.
        acc += __shfl_xor_sync(FULL, acc, 4);
        acc += __shfl_xor_sync(FULL, acc, 2);
        acc += __shfl_xor_sync(FULL, acc, 1);

        if (j == 0) {
            // Lanes 0,8,16,24 -> 4 consecutive floats, one wavefront.
            out[eo] = 1.0f / (1.0f + __expf(-acc));
        }
    }
}

extern "C" void kernel_launch(void* const* d_in, const int* in_sizes, int n_in,
                              void* d_out, int out_size)
{
    const float* z          = (const float*)d_in[0];
    const int*   edge_index = (const int*)d_in[1];
    const int*   rel_id     = (const int*)d_in[2];
    const float* rel        = (const float*)d_in[3];
    float*       out        = (float*)d_out;

    int nz = in_sizes[0];            // z element count (<= NZ_MAX)
    int nr = in_sizes[3];            // rel element count
    int E  = in_sizes[2];

    if (nz > NZ_MAX) nz = NZ_MAX;
    if (nr > NR_MAX) nr = NR_MAX;

    // 1) fp32 -> fp16 mirrors (8 floats per thread, one 16B store)
    {
        int work = (nz >> 3) + (nr >> 3);
        int threads = 256;
        int blocks = (work + threads - 1) / threads;
        convert_kernel<<<blocks, threads>>>(z, rel, nz, nr);
    }

    // 2) edge scoring (E assumed multiple of 32; full grid of 32-edge warps)
    {
        const int threads = 256;                 // 8 warps/block, 32 edges/warp
        int edges_per_block = (threads / 32) * 32;
        int blocks = (E + edges_per_block - 1) / edges_per_block;
        distmult_h<<<blocks, threads>>>(edge_index, rel_id, out, E);
    }
}

// round 14
// speedup vs baseline: 1.0294x; 1.0205x over previous
#include <cuda_runtime.h>
#include <cuda_fp16.h>
#include <cstdint>

// DistMult edge scorer:
//   out[e] = sigmoid( sum_d z[src,d] * rel[rel_id,d] * z[dst,d] )
// Inputs:
//   d_in[0]: z          float32 [100000, 128]
//   d_in[1]: edge_index int32   [2, E]
//   d_in[2]: rel_id     int32   [E]
//   d_in[3]: rel        float32 [64, 128]
// Output: float32 [E]
//
//  1) convert_kernel: z, rel -> fp16 mirrors (8 floats/thread, one 16B store).
//  2) distmult_h: 8 lanes/edge, 4 edges/warp-pass, unroll 2, HFMA2 math with
//     4 independent half2 accumulators. NEW: distance-1 software pipeline on
//     the index loads — pass m's data loads issue immediately, pass m+1's
//     index loads issue next, pass m's math covers their latency.

#define D 128
#define NZ_MAX (100000 * D)
#define NR_MAX (64 * D)
#define FULL 0xFFFFFFFFu

__device__ __half g_zh[NZ_MAX];
__device__ __half g_rh[NR_MAX];

// ---------------- conversion: fp32 -> fp16 mirrors ----------------
__device__ __forceinline__ uint4 cvt8(float4 v0, float4 v1) {
    __half2 h0 = __floats2half2_rn(v0.x, v0.y);
    __half2 h1 = __floats2half2_rn(v0.z, v0.w);
    __half2 h2 = __floats2half2_rn(v1.x, v1.y);
    __half2 h3 = __floats2half2_rn(v1.z, v1.w);
    uint4 o;
    o.x = *reinterpret_cast<unsigned*>(&h0);
    o.y = *reinterpret_cast<unsigned*>(&h1);
    o.z = *reinterpret_cast<unsigned*>(&h2);
    o.w = *reinterpret_cast<unsigned*>(&h3);
    return o;
}

__global__ __launch_bounds__(256) void convert_kernel(
    const float* __restrict__ z, const float* __restrict__ rel,
    int nz, int nr)
{
    int i = blockIdx.x * blockDim.x + threadIdx.x;   // 8 floats per thread
    int nz8 = nz >> 3;
    int nr8 = nr >> 3;
    if (i < nz8) {
        const float4* zp = reinterpret_cast<const float4*>(z);
        reinterpret_cast<uint4*>(g_zh)[i] = cvt8(zp[2 * i], zp[2 * i + 1]);
    } else if (i < nz8 + nr8) {
        int k = i - nz8;
        const float4* rp = reinterpret_cast<const float4*>(rel);
        reinterpret_cast<uint4*>(g_rh)[k] = cvt8(rp[2 * k], rp[2 * k + 1]);
    }
}

// ---------------- main kernel ----------------

__device__ __forceinline__ __half2 h2_of(unsigned u) {
    return *reinterpret_cast<__half2*>(&u);
}

__global__ __launch_bounds__(256) void distmult_h(
    const int* __restrict__ edge_index,  // [2, E]
    const int* __restrict__ rel_id,      // [E]
    float* __restrict__ out,
    int E)
{
    int warp_id = (blockIdx.x * blockDim.x + threadIdx.x) >> 5;
    int lane = threadIdx.x & 31;
    int g = lane >> 3;                   // edge group 0..3
    int j = lane & 7;                    // lane within group
    int base = warp_id << 5;             // 32 edges per warp
    if (base >= E) return;

    const uint4* zh = reinterpret_cast<const uint4*>(g_zh);  // 16 uint4 per row
    const uint4* rh = reinterpret_cast<const uint4*>(g_rh);

    // Pipeline prologue: pass 0's indices.
    int e = base + g;
    int s = edge_index[e];
    int d = edge_index[E + e];
    int r = rel_id[e];

    #pragma unroll 2
    for (int m = 0; m < 8; ++m) {
        const uint4* zs = zh + (size_t)s * 16;   // 256B row = 16 uint4
        const uint4* zd = zh + (size_t)d * 16;
        const uint4* rr = rh + (size_t)r * 16;

        // Pass m data loads: 6 independent LDG.128, each = 4 full 128B lines.
        uint4 A0 = zs[j], A1 = zs[j + 8];
        uint4 B0 = zd[j], B1 = zd[j + 8];
        uint4 C0 = rr[j], C1 = rr[j + 8];

        int eo = e;                      // edge this pass writes
        // Pass m+1 index loads (latency hidden by pass m math below).
        if (m < 7) {
            e = base + ((m + 1) << 2) + g;
            s = edge_index[e];
            d = edge_index[E + e];
            r = rel_id[e];
        }

        // 4 independent half2 accumulators; chains of length 2.
        __half2 acc0 = __hmul2(__hmul2(h2_of(A0.x), h2_of(C0.x)), h2_of(B0.x));
        __half2 acc1 = __hmul2(__hmul2(h2_of(A0.y), h2_of(C0.y)), h2_of(B0.y));
        __half2 acc2 = __hmul2(__hmul2(h2_of(A0.z), h2_of(C0.z)), h2_of(B0.z));
        __half2 acc3 = __hmul2(__hmul2(h2_of(A0.w), h2_of(C0.w)), h2_of(B0.w));
        acc0 = __hfma2(__hmul2(h2_of(A1.x), h2_of(C1.x)), h2_of(B1.x), acc0);
        acc1 = __hfma2(__hmul2(h2_of(A1.y), h2_of(C1.y)), h2_of(B1.y), acc1);
        acc2 = __hfma2(__hmul2(h2_of(A1.z), h2_of(C1.z)), h2_of(B1.z), acc2);
        acc3 = __hfma2(__hmul2(h2_of(A1.w), h2_of(C1.w)), h2_of(B1.w), acc3);

        // Pairwise fp16 combine, fp32 epilogue.
        __half2 s01 = __hadd2(acc0, acc1);
        __half2 s23 = __hadd2(acc2, acc3);
        float2 f01 = __half22float2(s01);
        float2 f23 = __half22float2(s23);
        float acc = (f01.x + f01.y) + (f23.x + f23.y);

        // Reduce over 8-lane group (fp32); 4 edges share the same 3 shfls.
        acc += __shfl_xor_sync(FULL, acc, 4);
        acc += __shfl_xor_sync(FULL, acc, 2);
        acc += __shfl_xor_sync(FULL, acc, 1);

        if (j == 0) {
            // Lanes 0,8,16,24 -> 4 consecutive floats, one wavefront.
            out[eo] = 1.0f / (1.0f + __expf(-acc));
        }
    }
}

extern "C" void kernel_launch(void* const* d_in, const int* in_sizes, int n_in,
                              void* d_out, int out_size)
{
    const float* z          = (const float*)d_in[0];
    const int*   edge_index = (const int*)d_in[1];
    const int*   rel_id     = (const int*)d_in[2];
    const float* rel        = (const float*)d_in[3];
    float*       out        = (float*)d_out;

    int nz = in_sizes[0];            // z element count (<= NZ_MAX)
    int nr = in_sizes[3];            // rel element count
    int E  = in_sizes[2];

    if (nz > NZ_MAX) nz = NZ_MAX;
    if (nr > NR_MAX) nr = NR_MAX;

    // 1) fp32 -> fp16 mirrors (8 floats per thread, one 16B store)
    {
        int work = (nz >> 3) + (nr >> 3);
        int threads = 256;
        int blocks = (work + threads - 1) / threads;
        convert_kernel<<<blocks, threads>>>(z, rel, nz, nr);
    }

    // 2) edge scoring (E assumed multiple of 32; full grid of 32-edge warps)
    {
        const int threads = 256;                 // 8 warps/block, 32 edges/warp
        int edges_per_block = (threads / 32) * 32;
        int blocks = (E + edges_per_block - 1) / edges_per_block;
        distmult_h<<<blocks, threads>>>(edge_index, rel_id, out, E);
    }
}